// round 7
// baseline (speedup 1.0000x reference)
#include <cuda_runtime.h>
#include <cstdint>

#define TT 2048
#define BB 512
#define KK 8
#define DD 32
#define DT_F 0.05f
#define SQDT_F 0.22360679774997896f  /* sqrt(0.05) */
#define UN 2                          /* prefetch group / unroll */

// Scratch: normalized weights wn[t][b][k] = s_probs / sum_k. Static (no allocs).
__device__ float g_wn[TT * BB * KK];

// ---------- f32x2 helpers (FFMA2 is PTX-only on sm_103a) ----------
__device__ __forceinline__ unsigned long long add2(unsigned long long a, unsigned long long b) {
    unsigned long long d;
    asm("add.rn.f32x2 %0, %1, %2;" : "=l"(d) : "l"(a), "l"(b));
    return d;
}
__device__ __forceinline__ void ffma2(unsigned long long& d, unsigned long long a, unsigned long long b) {
    asm("fma.rn.f32x2 %0, %1, %2, %3;" : "=l"(d) : "l"(a), "l"(b), "l"(d));
}
__device__ __forceinline__ float hsum2(unsigned long long v) {
    float lo, hi;
    asm("mov.b64 {%0, %1}, %2;" : "=f"(lo), "=f"(hi) : "l"(v));
    return lo + hi;
}

// ---------- Kernel 1: normalized weights ----------
__global__ void __launch_bounds__(256) norm_kernel(const float* __restrict__ s_probs) {
    int idx = blockIdx.x * blockDim.x + threadIdx.x;  // (t,b) pair
    if (idx < TT * BB) {
        const float4* p = (const float4*)(s_probs + (size_t)idx * KK);
        float4 a = p[0];
        float4 b = p[1];
        float s = ((a.x + a.y) + (a.z + a.w)) + ((b.x + b.y) + (b.z + b.w));
        float r = 1.0f / s;
        float4* o = (float4*)(g_wn + (size_t)idx * KK);
        o[0] = make_float4(a.x * r, a.y * r, a.z * r, a.w * r);
        o[1] = make_float4(b.x * r, b.y * r, b.z * r, b.w * r);
    }
}

// ---------- Kernel 2: one CTA (128 thr = 4 warps) per FOUR batches ----------
// Warp w: pr = w>>1 selects the batch pair {b0,b1}; wp = w&1 selects the
// k-half (kb = 4*wp). A rows live once in registers and are shared by BOTH
// batches of the pair -> 128 FFMA2 per warp per step in 8 independent chains
// (one warp saturates its SMSP's fma pipe alone). Cross-warp k-reduction =
// one float2 smem exchange, parity-buffered, 1 __syncthreads per step.
__global__ void __launch_bounds__(128, 1) sde_main(
    const float* __restrict__ z0,
    const float* __restrict__ noise,
    const float* __restrict__ A_s,
    const float* __restrict__ b_s,
    const float* __restrict__ Q_chol,
    float* __restrict__ ys)
{
    const int tid  = threadIdx.x;
    const int w    = tid >> 5;       // 0..3
    const int lane = tid & 31;       // row i
    const int pr   = w >> 1;         // batch pair within CTA
    const int wp   = w & 1;          // k-half
    const int kb   = wp * 4;         // k base
    const int b0   = blockIdx.x * 4 + pr * 2;
    const int b1   = b0 + 1;

    __shared__ __align__(16) float  zbuf[2][2][2][DD];     // [pr][wp][batch][row]
    __shared__ __align__(16) float2 pbuf[2][2][2][2][DD];  // [parity][pr][wp][batch][row]

    // ---- A rows -> registers as f32x2 pairs: A[kk] = row `lane` of A_{kb+kk} ----
    unsigned long long A[4][16];
#pragma unroll
    for (int kk = 0; kk < 4; kk++) {
        const ulonglong2* r = (const ulonglong2*)(A_s + (size_t)((kb + kk) * DD + lane) * DD);
#pragma unroll
        for (int q = 0; q < 8; q++) {
            ulonglong2 v = r[q];
            A[kk][2 * q]     = v.x;
            A[kk][2 * q + 1] = v.y;
        }
    }
    float dtb[4], qc[4];
#pragma unroll
    for (int kk = 0; kk < 4; kk++) {
        dtb[kk] = DT_F * b_s[(kb + kk) * DD + lane];
        qc[kk]  = Q_chol[(kb + kk) * DD + lane];
    }

    // ---- z init (both batches) ----
    float zr0 = z0[(size_t)b0 * DD + lane];
    float zr1 = z0[(size_t)b1 * DD + lane];
    zbuf[pr][wp][0][lane] = zr0;
    zbuf[pr][wp][1][lane] = zr1;

    // stream pointers
    const float4* wp4 = (const float4*)g_wn;             // ((t*BB+b)*KK)/4 + wp
    const float*  np0 = noise + (size_t)b0 * DD + lane;
    const float*  np1 = noise + (size_t)b1 * DD + lane;
    float*        yp0 = ys    + (size_t)b0 * DD + lane;
    float*        yp1 = ys    + (size_t)b1 * DD + lane;

    // ---- prefetch group 0 ----
    float4 w4_c[2][UN]; float dw_c[2][UN];
#pragma unroll
    for (int u = 0; u < UN; u++) {
        w4_c[0][u] = __ldg(&wp4[((size_t)u * BB + b0) * 2 + wp]);
        w4_c[1][u] = __ldg(&wp4[((size_t)u * BB + b1) * 2 + wp]);
        dw_c[0][u] = SQDT_F * __ldg(&np0[(size_t)u * (BB * DD)]);
        dw_c[1][u] = SQDT_F * __ldg(&np1[(size_t)u * (BB * DD)]);
    }

    __syncthreads();

    for (int s0 = 0; s0 < TT; s0 += UN) {
        // ---- prefetch next group (clamped; last-group values unused) ----
        float4 w4_n[2][UN]; float dw_n[2][UN];
#pragma unroll
        for (int u = 0; u < UN; u++) {
            int ts = s0 + UN + u;
            if (ts >= TT) ts = TT - 1;
            w4_n[0][u] = __ldg(&wp4[((size_t)ts * BB + b0) * 2 + wp]);
            w4_n[1][u] = __ldg(&wp4[((size_t)ts * BB + b1) * 2 + wp]);
            dw_n[0][u] = SQDT_F * __ldg(&np0[(size_t)ts * (BB * DD)]);
            dw_n[1][u] = SQDT_F * __ldg(&np1[(size_t)ts * (BB * DD)]);
        }

#pragma unroll
        for (int u = 0; u < UN; u++) {
            const int step = s0 + u;
            const int par  = step & 1;

            // ---- matvecs for BOTH batches: 16 LDS.128 + 128 FFMA2, 8 chains ----
            unsigned long long acc0[8], acc1[8];
#pragma unroll
            for (int q = 0; q < 8; q++) { acc0[q] = 0ull; acc1[q] = 0ull; }
            const ulonglong2* zvA = (const ulonglong2*)(&zbuf[pr][wp][0][0]);
            const ulonglong2* zvB = (const ulonglong2*)(&zbuf[pr][wp][1][0]);
#pragma unroll
            for (int jj = 0; jj < 8; jj++) {
                ulonglong2 zA = zvA[jj];
                ulonglong2 zB = zvB[jj];
#pragma unroll
                for (int kk = 0; kk < 4; kk++) {
                    ffma2(acc0[kk],     A[kk][2 * jj],     zA.x);
                    ffma2(acc0[kk + 4], A[kk][2 * jj + 1], zA.y);
                    ffma2(acc1[kk],     A[kk][2 * jj],     zB.x);
                    ffma2(acc1[kk + 4], A[kk][2 * jj + 1], zB.y);
                }
            }

            // ---- per-batch weighted combine over the warp's 4 k's ----
            float4 wv0 = w4_c[0][u];
            float4 wv1 = w4_c[1][u];
            float a00 = hsum2(add2(acc0[0], acc0[4]));
            float a01 = hsum2(add2(acc0[1], acc0[5]));
            float a02 = hsum2(add2(acc0[2], acc0[6]));
            float a03 = hsum2(add2(acc0[3], acc0[7]));
            float a10 = hsum2(add2(acc1[0], acc1[4]));
            float a11 = hsum2(add2(acc1[1], acc1[5]));
            float a12 = hsum2(add2(acc1[2], acc1[6]));
            float a13 = hsum2(add2(acc1[3], acc1[7]));

            float pd0 = fmaf(wv0.x, fmaf(DT_F, a00, dtb[0]),
                        fmaf(wv0.y, fmaf(DT_F, a01, dtb[1]),
                        fmaf(wv0.z, fmaf(DT_F, a02, dtb[2]),
                             wv0.w * fmaf(DT_F, a03, dtb[3]))));
            float pq0 = fmaf(wv0.x, qc[0], fmaf(wv0.y, qc[1],
                        fmaf(wv0.z, qc[2], wv0.w * qc[3])));
            float pd1 = fmaf(wv1.x, fmaf(DT_F, a10, dtb[0]),
                        fmaf(wv1.y, fmaf(DT_F, a11, dtb[1]),
                        fmaf(wv1.z, fmaf(DT_F, a12, dtb[2]),
                             wv1.w * fmaf(DT_F, a13, dtb[3]))));
            float pq1 = fmaf(wv1.x, qc[0], fmaf(wv1.y, qc[1],
                        fmaf(wv1.z, qc[2], wv1.w * qc[3])));

            // ---- cross-warp k-reduction: parity smem exchange + 1 barrier ----
            pbuf[par][pr][wp][0][lane] = make_float2(pd0, pq0);
            pbuf[par][pr][wp][1][lane] = make_float2(pd1, pq1);
            __syncthreads();
            float2 o0 = pbuf[par][pr][wp ^ 1][0][lane];
            float2 o1 = pbuf[par][pr][wp ^ 1][1][lane];

            // ---- z update (both warps of the pair redundantly) ----
            zr0 = fmaf(pq0 + o0.y, dw_c[0][u], zr0 + (pd0 + o0.x));
            zr1 = fmaf(pq1 + o1.y, dw_c[1][u], zr1 + (pd1 + o1.x));
            zbuf[pr][wp][0][lane] = zr0;
            zbuf[pr][wp][1][lane] = zr1;
            if (wp == 0) {
                yp0[(size_t)step * (BB * DD)] = zr0;   // coalesced 128B
                yp1[(size_t)step * (BB * DD)] = zr1;
            }
            __syncwarp();
        }

        // rotate prefetch buffers
#pragma unroll
        for (int u = 0; u < UN; u++) {
            w4_c[0][u] = w4_n[0][u];
            w4_c[1][u] = w4_n[1][u];
            dw_c[0][u] = dw_n[0][u];
            dw_c[1][u] = dw_n[1][u];
        }
    }
}

extern "C" void kernel_launch(void* const* d_in, const int* in_sizes, int n_in,
                              void* d_out, int out_size) {
    const float* z0      = (const float*)d_in[0];
    const float* s_probs = (const float*)d_in[1];
    const float* noise   = (const float*)d_in[2];
    const float* A_s     = (const float*)d_in[3];
    const float* b_s     = (const float*)d_in[4];
    const float* Q_chol  = (const float*)d_in[5];
    float*       ys      = (float*)d_out;

    norm_kernel<<<(TT * BB + 255) / 256, 256>>>(s_probs);
    sde_main<<<BB / 4, 128>>>(z0, noise, A_s, b_s, Q_chol, ys);
}

// round 8
// speedup vs baseline: 1.2052x; 1.2052x over previous
#include <cuda_runtime.h>
#include <cstdint>

#define TT 2048
#define BB 512
#define KK 8
#define DD 32
#define DT_F 0.05f
#define SQDT_F 0.22360679774997896f  /* sqrt(0.05) */
#define UN 2                          /* prefetch group / unroll */

// Scratch: normalized weights, re-packed so warp q reads (w_q, w_{q+4}) as
// one float2:  g_wn[((t*BB + b)*4 + q)*2 + {0,1}] = (s_q, s_{q+4}) / sum.
__device__ float g_wn[TT * BB * KK];

// ---------- f32x2 helpers (FFMA2 is PTX-only on sm_103a) ----------
__device__ __forceinline__ unsigned long long add2(unsigned long long a, unsigned long long b) {
    unsigned long long d;
    asm("add.rn.f32x2 %0, %1, %2;" : "=l"(d) : "l"(a), "l"(b));
    return d;
}
__device__ __forceinline__ void ffma2(unsigned long long& d, unsigned long long a, unsigned long long b) {
    asm("fma.rn.f32x2 %0, %1, %2, %3;" : "=l"(d) : "l"(a), "l"(b), "l"(d));
}
__device__ __forceinline__ float hsum2(unsigned long long v) {
    float lo, hi;
    asm("mov.b64 {%0, %1}, %2;" : "=f"(lo), "=f"(hi) : "l"(v));
    return lo + hi;
}
__device__ __forceinline__ void unpack2(unsigned long long v, float& lo, float& hi) {
    asm("mov.b64 {%0, %1}, %2;" : "=f"(lo), "=f"(hi) : "l"(v));
}

// ---------- Kernel 1: normalized weights, (q, q+4)-interleaved packing ----------
__global__ void __launch_bounds__(256) norm_kernel(const float* __restrict__ s_probs) {
    int idx = blockIdx.x * blockDim.x + threadIdx.x;  // (t,b) pair
    if (idx < TT * BB) {
        const float4* p = (const float4*)(s_probs + (size_t)idx * KK);
        float4 a = p[0];   // s0..s3
        float4 b = p[1];   // s4..s7
        float s = ((a.x + a.y) + (a.z + a.w)) + ((b.x + b.y) + (b.z + b.w));
        float r = 1.0f / s;
        float4* o = (float4*)(g_wn + (size_t)idx * KK);
        // pairs: (s0,s4) (s1,s5) | (s2,s6) (s3,s7)
        o[0] = make_float4(a.x * r, b.x * r, a.y * r, b.y * r);
        o[1] = make_float4(a.z * r, b.z * r, a.w * r, b.w * r);
    }
}

// ---------- Kernel 2: one CTA (128 thr = 4 warps) per batch ----------
// Warp q owns rows of A_q and A_{q+4} (64 regs). All 4 warps land on the 4
// SMSPs; regs capped at 128 so 4 CTAs/SM -> 4 warps per SMSP (latency hiding)
// with ALL SMSPs active. One __syncthreads per step (the k-reduction); each
// warp keeps a private z copy so the post-update publish needs no barrier.
__global__ void __launch_bounds__(128, 4) sde_main(
    const float* __restrict__ z0,
    const float* __restrict__ noise,
    const float* __restrict__ A_s,
    const float* __restrict__ b_s,
    const float* __restrict__ Q_chol,
    float* __restrict__ ys)
{
    const int b    = blockIdx.x;
    const int tid  = threadIdx.x;
    const int q    = tid >> 5;       // warp id 0..3 -> k pair {q, q+4}
    const int lane = tid & 31;       // row i
    const int k0   = q;
    const int k1   = q + 4;

    __shared__ __align__(16) float  zbuf[2][4][DD];   // [parity][warp][row] private z
    __shared__ __align__(16) float2 pbuf[2][4][DD];   // [parity][warp][row] partials

    // ---- A rows -> registers as f32x2 pairs ----
    unsigned long long Aa[16], Ab[16];
    {
        const ulonglong2* r0 = (const ulonglong2*)(A_s + (size_t)(k0 * DD + lane) * DD);
        const ulonglong2* r1 = (const ulonglong2*)(A_s + (size_t)(k1 * DD + lane) * DD);
#pragma unroll
        for (int p = 0; p < 8; p++) {
            ulonglong2 v0 = r0[p]; Aa[2 * p] = v0.x; Aa[2 * p + 1] = v0.y;
            ulonglong2 v1 = r1[p]; Ab[2 * p] = v1.x; Ab[2 * p + 1] = v1.y;
        }
    }
    const float dtb0 = DT_F * b_s[k0 * DD + lane];
    const float dtb1 = DT_F * b_s[k1 * DD + lane];
    const float qc0  = Q_chol[k0 * DD + lane];
    const float qc1  = Q_chol[k1 * DD + lane];

    // ---- z init ----
    float zreg = z0[(size_t)b * DD + lane];
    zbuf[0][q][lane] = zreg;

    // stream pointers
    const float2* wp2 = (const float2*)g_wn;          // ((t*BB+b)*4 + q)
    const float*  np  = noise + (size_t)b * DD + lane;
    float*        yp  = ys    + (size_t)b * DD + lane;

    // ---- prefetch group 0 ----
    float2 wv_c[UN]; float dw_c[UN];
#pragma unroll
    for (int u = 0; u < UN; u++) {
        wv_c[u] = __ldg(&wp2[((size_t)u * BB + b) * 4 + q]);
        dw_c[u] = SQDT_F * __ldg(&np[(size_t)u * (BB * DD)]);
    }

    __syncthreads();

    for (int s0 = 0; s0 < TT; s0 += UN) {
        // ---- prefetch next group (clamped; last-group values unused) ----
        float2 wv_n[UN]; float dw_n[UN];
#pragma unroll
        for (int u = 0; u < UN; u++) {
            int ts = s0 + UN + u;
            if (ts >= TT) ts = TT - 1;
            wv_n[u] = __ldg(&wp2[((size_t)ts * BB + b) * 4 + q]);
            dw_n[u] = SQDT_F * __ldg(&np[(size_t)ts * (BB * DD)]);
        }

#pragma unroll
        for (int u = 0; u < UN; u++) {
            const int step = s0 + u;
            const int par  = step & 1;

            // ---- matvec: rows of A_q, A_{q+4} vs z (8 LDS.128 + 32 FFMA2) ----
            unsigned long long c0a = 0ull, c0b = 0ull, c1a = 0ull, c1b = 0ull;
            const ulonglong2* zv = (const ulonglong2*)(&zbuf[par][q][0]);
#pragma unroll
            for (int jj = 0; jj < 8; jj++) {
                ulonglong2 z2 = zv[jj];                 // LDS.128 broadcast
                ffma2(c0a, Aa[2 * jj],     z2.x);
                ffma2(c0b, Aa[2 * jj + 1], z2.y);
                ffma2(c1a, Ab[2 * jj],     z2.x);
                ffma2(c1b, Ab[2 * jj + 1], z2.y);
            }
            float a0 = hsum2(add2(c0a, c0b));
            float a1 = hsum2(add2(c1a, c1b));

            // ---- combine this warp's two k's (register math) ----
            float2 wv = wv_c[u];
            float pd = fmaf(wv.x, fmaf(DT_F, a0, dtb0),
                            wv.y * fmaf(DT_F, a1, dtb1));
            float pq = fmaf(wv.x, qc0, wv.y * qc1);

            // ---- cross-warp k-reduction: STS + 1 barrier + 4 LDS.64 ----
            pbuf[par][q][lane] = make_float2(pd, pq);
            __syncthreads();
            float2 p0 = pbuf[par][0][lane];
            float2 p1 = pbuf[par][1][lane];
            float2 p2 = pbuf[par][2][lane];
            float2 p3 = pbuf[par][3][lane];
            float sd = (p0.x + p1.x) + (p2.x + p3.x);
            float sq = (p0.y + p1.y) + (p2.y + p3.y);

            // ---- z update (all warps redundantly; each publishes own copy) ----
            zreg = fmaf(sq, dw_c[u], zreg + sd);
            zbuf[par ^ 1][q][lane] = zreg;
            if (q == 0) yp[(size_t)step * (BB * DD)] = zreg;  // coalesced 128B
        }

        // rotate prefetch buffers
#pragma unroll
        for (int u = 0; u < UN; u++) {
            wv_c[u] = wv_n[u];
            dw_c[u] = dw_n[u];
        }
    }
}

extern "C" void kernel_launch(void* const* d_in, const int* in_sizes, int n_in,
                              void* d_out, int out_size) {
    const float* z0      = (const float*)d_in[0];
    const float* s_probs = (const float*)d_in[1];
    const float* noise   = (const float*)d_in[2];
    const float* A_s     = (const float*)d_in[3];
    const float* b_s     = (const float*)d_in[4];
    const float* Q_chol  = (const float*)d_in[5];
    float*       ys      = (float*)d_out;

    norm_kernel<<<(TT * BB + 255) / 256, 256>>>(s_probs);
    sde_main<<<BB, 128>>>(z0, noise, A_s, b_s, Q_chol, ys);
}